// round 2
// baseline (speedup 1.0000x reference)
#include <cuda_runtime.h>
#include <cuda_bf16.h>

typedef unsigned int u32;
typedef unsigned long long u64;

#define THREADS 256
#define ROWS 32
#define CTAS 128
#define TSTEPS 64
#define KD 192
#define DT 0.01f

// ---------- shared memory layout (units of 4 bytes) ----------
#define P_W1 193   // pitch for K=192 weight rows (193 % 32 = 1 -> conflict-free)
#define P_W2 129   // pitch for K=128 weight rows
#define P_RW2 65   // pitch for K=64 weight rows
#define P_ACT 66   // pitch for duplicated activations: [col][2*ROWS + pad]

#define OFF_CW1 0
#define OFF_CW2 (OFF_CW1 + 64 * P_W1)
#define OFF_RW1 (OFF_CW2 + 64 * P_W2)
#define OFF_RW2 (OFF_RW1 + 32 * P_W1)
#define OFF_CB1 (OFF_RW2 + 32 * P_RW2)
#define OFF_CB2 (OFF_CB1 + 128)
#define OFF_RB1 (OFF_CB2 + 128)
#define OFF_RB2 (OFF_RB1 + 64)
#define OFF_Y   (OFF_RB2 + 64)
#define OFF_H1  (OFF_Y  + 192 * P_ACT)
#define OFF_R1  (OFF_H1 + 128 * P_ACT)
#define SMEM_FLOATS (OFF_R1 + 64 * P_ACT)
#define SMEM_BYTES (SMEM_FLOATS * 4)   // 218368 bytes <= 227KB opt-in limit

// ---------- packed f32x2 helpers ----------
__device__ __forceinline__ u64 ffma2(u64 a, u64 b, u64 c) {
    u64 d;
    asm("fma.rn.f32x2 %0, %1, %2, %3;" : "=l"(d) : "l"(a), "l"(b), "l"(c));
    return d;
}
// bf16x2 (lo = col 2q, hi = col 2q+1) -> f32x2
__device__ __forceinline__ u64 bf2(u32 v) {
    u32 lo = v << 16;
    u32 hi = v & 0xFFFF0000u;
    u64 r;
    asm("mov.b64 %0, {%1, %2};" : "=l"(r) : "r"(lo), "r"(hi));
    return r;
}
__device__ __forceinline__ u64 pack2(float a, float b) {
    u64 r;
    asm("mov.b64 %0, {%1, %2};" : "=l"(r) : "f"(a), "f"(b));
    return r;
}
__device__ __forceinline__ u64 dup2(float a) { return pack2(a, a); }
__device__ __forceinline__ void unpk(u64 v, float& a, float& b) {
    asm("mov.b64 {%0, %1}, %2;" : "=f"(a), "=f"(b) : "l"(v));
}
__device__ __forceinline__ u32 pkbf(float a, float b) {
    __nv_bfloat162 h = __floats2bfloat162_rn(a, b);  // .x=a (low), .y=b (high)
    return *reinterpret_cast<u32*>(&h);
}

// ---------- inner GEMM fragments ----------
// Output cols are pair-packed: acc[rr][j] holds (col 2q, col 2q+1) for q = lane + 32*j.
// ys points at duplicated activations for this thread's 4 rows: value (k, r) at ys[k*P_ACT + 2*rr].
template<int KDIM>
__device__ __forceinline__ void gemm_pair2(const u32* __restrict__ wa,
                                           const u32* __restrict__ wb,
                                           const float* __restrict__ ys,
                                           u64 acc[4][2]) {
#pragma unroll 8
    for (int k = 0; k < KDIM; ++k) {
        u64 w2a = bf2(wa[k]);
        u64 w2b = bf2(wb[k]);
        const float* yk = ys + k * P_ACT;
#pragma unroll
        for (int rr = 0; rr < 4; ++rr) {
            u64 y2 = *(const u64*)(yk + 2 * rr);
            acc[rr][0] = ffma2(y2, w2a, acc[rr][0]);
            acc[rr][1] = ffma2(y2, w2b, acc[rr][1]);
        }
    }
}
template<int KDIM>
__device__ __forceinline__ void gemm_pair1(const u32* __restrict__ wa,
                                           const float* __restrict__ ys,
                                           u64 acc[4]) {
#pragma unroll 8
    for (int k = 0; k < KDIM; ++k) {
        u64 w2a = bf2(wa[k]);
        const float* yk = ys + k * P_ACT;
#pragma unroll
        for (int rr = 0; rr < 4; ++rr) {
            u64 y2 = *(const u64*)(yk + 2 * rr);
            acc[rr] = ffma2(y2, w2a, acc[rr]);
        }
    }
}

__global__ __launch_bounds__(THREADS, 1)
void koopman_kernel(const float* __restrict__ x,
                    const float* __restrict__ cW1, const float* __restrict__ cb1,
                    const float* __restrict__ cW2, const float* __restrict__ cb2,
                    const float* __restrict__ rW1, const float* __restrict__ rb1,
                    const float* __restrict__ rW2, const float* __restrict__ rb2,
                    float* __restrict__ out) {
    extern __shared__ float sm[];
    u32* scw1 = (u32*)(sm + OFF_CW1);
    u32* scw2 = (u32*)(sm + OFF_CW2);
    u32* srw1 = (u32*)(sm + OFF_RW1);
    u32* srw2 = (u32*)(sm + OFF_RW2);
    float* sy  = sm + OFF_Y;
    float* sh1 = sm + OFF_H1;
    float* sr1 = sm + OFF_R1;

    const int tid = threadIdx.x;

    // ---- pack weights to bf16x2 pair-interleaved layout ----
    for (int i = tid; i < 64 * 192; i += THREADS) {
        int q = i / 192, k = i % 192;
        scw1[q * P_W1 + k] = pkbf(cW1[(2 * q) * 192 + k], cW1[(2 * q + 1) * 192 + k]);
    }
    for (int i = tid; i < 64 * 128; i += THREADS) {
        int q = i / 128, k = i % 128;
        scw2[q * P_W2 + k] = pkbf(cW2[(2 * q) * 128 + k], cW2[(2 * q + 1) * 128 + k]);
    }
    for (int i = tid; i < 32 * 192; i += THREADS) {
        int q = i / 192, k = i % 192;
        srw1[q * P_W1 + k] = pkbf(rW1[(2 * q) * 192 + k], rW1[(2 * q + 1) * 192 + k]);
    }
    for (int i = tid; i < 32 * 64; i += THREADS) {
        int q = i / 64, k = i % 64;
        srw2[q * P_RW2 + k] = pkbf(rW2[(2 * q) * 64 + k], rW2[(2 * q + 1) * 64 + k]);
    }
    if (tid < 128) {
        sm[OFF_CB1 + tid] = cb1[tid];
        sm[OFF_CB2 + tid] = cb2[tid];
    }
    if (tid < 64) {
        sm[OFF_RB1 + tid] = rb1[tid];
        sm[OFF_RB2 + tid] = rb2[tid];
    }

    // ---- init duplicated y state from x[:, 0, :] ----
    const int rowBase = blockIdx.x * ROWS;
    for (int i = tid; i < ROWS * KD; i += THREADS) {
        int r = i / KD, c = i % KD;
        float v = x[(size_t)(rowBase + r) * (TSTEPS * KD) + c];
        sy[c * P_ACT + 2 * r]     = v;
        sy[c * P_ACT + 2 * r + 1] = v;
    }
    __syncthreads();

    const int lane = tid & 31;
    const int r0   = (tid >> 5) * 4;          // 8 warps * 4 rows = 32 rows
    const float* ysA = sy  + 2 * r0;
    const float* h1A = sh1 + 2 * r0;
    const float* r1A = sr1 + 2 * r0;
    const u32* w1a = scw1 + lane * P_W1;
    const u32* w1b = scw1 + (lane + 32) * P_W1;
    const u32* w2a = scw2 + lane * P_W2;
    const u32* w2b = scw2 + (lane + 32) * P_W2;
    const u32* rw1a = srw1 + lane * P_W1;
    const u32* rw2a = srw2 + lane * P_RW2;

    const u64 bc1a = pack2(sm[OFF_CB1 + 2 * lane],      sm[OFF_CB1 + 2 * lane + 1]);
    const u64 bc1b = pack2(sm[OFF_CB1 + 2 * lane + 64], sm[OFF_CB1 + 2 * lane + 65]);
    const u64 bc2a = pack2(sm[OFF_CB2 + 2 * lane],      sm[OFF_CB2 + 2 * lane + 1]);
    const u64 bc2b = pack2(sm[OFF_CB2 + 2 * lane + 64], sm[OFF_CB2 + 2 * lane + 65]);
    const u64 br1  = pack2(sm[OFF_RB1 + 2 * lane],      sm[OFF_RB1 + 2 * lane + 1]);
    const u64 br2  = pack2(sm[OFF_RB2 + 2 * lane],      sm[OFF_RB2 + 2 * lane + 1]);

    float* outRow = out + (size_t)rowBase * TSTEPS * KD;

    for (int t = 0; t < TSTEPS; ++t) {
        // ---- Phase A1: h1 = relu(y @ cW1^T + cb1) ----
        u64 acc[4][2];
#pragma unroll
        for (int rr = 0; rr < 4; ++rr) { acc[rr][0] = bc1a; acc[rr][1] = bc1b; }
        gemm_pair2<192>(w1a, w1b, ysA, acc);
#pragma unroll
        for (int rr = 0; rr < 4; ++rr) {
            float a, b;
            unpk(acc[rr][0], a, b);
            a = fmaxf(a, 0.f); b = fmaxf(b, 0.f);
            *(u64*)(sh1 + (2 * lane) * P_ACT + 2 * (r0 + rr))      = dup2(a);
            *(u64*)(sh1 + (2 * lane + 1) * P_ACT + 2 * (r0 + rr))  = dup2(b);
            unpk(acc[rr][1], a, b);
            a = fmaxf(a, 0.f); b = fmaxf(b, 0.f);
            *(u64*)(sh1 + (2 * lane + 64) * P_ACT + 2 * (r0 + rr)) = dup2(a);
            *(u64*)(sh1 + (2 * lane + 65) * P_ACT + 2 * (r0 + rr)) = dup2(b);
        }
        // ---- Phase A2: r1 = relu(y @ rW1^T + rb1) ----
        u64 accr[4];
#pragma unroll
        for (int rr = 0; rr < 4; ++rr) accr[rr] = br1;
        gemm_pair1<192>(rw1a, ysA, accr);
#pragma unroll
        for (int rr = 0; rr < 4; ++rr) {
            float a, b;
            unpk(accr[rr], a, b);
            a = fmaxf(a, 0.f); b = fmaxf(b, 0.f);
            *(u64*)(sr1 + (2 * lane) * P_ACT + 2 * (r0 + rr))     = dup2(a);
            *(u64*)(sr1 + (2 * lane + 1) * P_ACT + 2 * (r0 + rr)) = dup2(b);
        }
        __syncthreads();

        // ---- Phase B: h = h1 @ cW2^T + cb2 ; re = r1 @ rW2^T + rb2 (registers) ----
#pragma unroll
        for (int rr = 0; rr < 4; ++rr) { acc[rr][0] = bc2a; acc[rr][1] = bc2b; }
        gemm_pair2<128>(w2a, w2b, h1A, acc);
#pragma unroll
        for (int rr = 0; rr < 4; ++rr) accr[rr] = br2;
        gemm_pair1<64>(rw2a, r1A, accr);

        // ---- Phase C: apply Koopman operator, update y in place, write out ----
#pragma unroll
        for (int j = 0; j < 2; ++j) {
            int q = lane + 32 * j;
#pragma unroll
            for (int rr = 0; rr < 4; ++rr) {
                float mu, om;
                unpk(acc[rr][j], mu, om);
                float e = __expf(DT * mu);
                float s, c;
                __sincosf(DT * om, &s, &c);
                int yi = 2 * (r0 + rr);
                float ye = sy[(2 * q) * P_ACT + yi];
                float yo = sy[(2 * q + 1) * P_ACT + yi];
                float ne = e * (c * ye - s * yo);
                float no = e * (s * ye + c * yo);
                *(u64*)(sy + (2 * q) * P_ACT + yi)     = dup2(ne);
                *(u64*)(sy + (2 * q + 1) * P_ACT + yi) = dup2(no);
                *(float2*)(outRow + (size_t)(r0 + rr) * (TSTEPS * KD) + (size_t)t * KD + 2 * q)
                    = make_float2(ne, no);
            }
        }
#pragma unroll
        for (int rr = 0; rr < 4; ++rr) {
            float ra, rb;
            unpk(accr[rr], ra, rb);
            int c0 = 128 + 2 * lane;
            int yi = 2 * (r0 + rr);
            float ya = sy[c0 * P_ACT + yi];
            float yb = sy[(c0 + 1) * P_ACT + yi];
            float na = ya * __expf(DT * ra);
            float nb = yb * __expf(DT * rb);
            *(u64*)(sy + c0 * P_ACT + yi)       = dup2(na);
            *(u64*)(sy + (c0 + 1) * P_ACT + yi) = dup2(nb);
            *(float2*)(outRow + (size_t)(r0 + rr) * (TSTEPS * KD) + (size_t)t * KD + c0)
                = make_float2(na, nb);
        }
        __syncthreads();
    }
}

extern "C" void kernel_launch(void* const* d_in, const int* in_sizes, int n_in,
                              void* d_out, int out_size) {
    const float* x   = (const float*)d_in[0];
    const float* cW1 = (const float*)d_in[1];
    const float* cb1 = (const float*)d_in[2];
    const float* cW2 = (const float*)d_in[3];
    const float* cb2 = (const float*)d_in[4];
    const float* rW1 = (const float*)d_in[5];
    const float* rb1 = (const float*)d_in[6];
    const float* rW2 = (const float*)d_in[7];
    const float* rb2 = (const float*)d_in[8];
    float* out = (float*)d_out;

    cudaFuncSetAttribute(koopman_kernel,
                         cudaFuncAttributeMaxDynamicSharedMemorySize, SMEM_BYTES);
    koopman_kernel<<<CTAS, THREADS, SMEM_BYTES>>>(x, cW1, cb1, cW2, cb2,
                                                  rW1, rb1, rW2, rb2, out);
}

// round 3
// speedup vs baseline: 1.1283x; 1.1283x over previous
#include <cuda_runtime.h>
#include <cuda_bf16.h>

typedef unsigned int u32;
typedef unsigned long long u64;

#define THREADS 256
#define ROWS 32
#define CTAS 128
#define TSTEPS 64
#define KD 192
#define DT 0.01f

// ---------- shared memory layout (units of 4 bytes) ----------
// Weight pitches even (8B-aligned LDS.64 of 2 k's) and ==2 mod 32 (conflict-free).
#define P_W1 194
#define P_W2 130
#define P_RW2 66
// Activation pitch multiple of 4 (16B-aligned LDS.128 of dup pairs).
#define P_ACT 68

#define OFF_CW1 0
#define OFF_CW2 (OFF_CW1 + 64 * P_W1)
#define OFF_RW1 (OFF_CW2 + 64 * P_W2)
#define OFF_RW2 (OFF_RW1 + 32 * P_W1)
#define OFF_CB1 (OFF_RW2 + 32 * P_RW2)
#define OFF_CB2 (OFF_CB1 + 128)
#define OFF_RB1 (OFF_CB2 + 128)
#define OFF_RB2 (OFF_RB1 + 64)
#define OFF_Y   (OFF_RB2 + 64)
#define OFF_H1  (OFF_Y  + 192 * P_ACT)
#define OFF_R1  (OFF_H1 + 128 * P_ACT)
#define SMEM_FLOATS (OFF_R1 + 64 * P_ACT)
#define SMEM_BYTES (SMEM_FLOATS * 4)   // 222208 bytes <= 227KB opt-in limit

// ---------- packed f32x2 helpers ----------
__device__ __forceinline__ u64 ffma2(u64 a, u64 b, u64 c) {
    u64 d;
    asm("fma.rn.f32x2 %0, %1, %2, %3;" : "=l"(d) : "l"(a), "l"(b), "l"(c));
    return d;
}
// bf16x2 (lo = col 2q, hi = col 2q+1) -> f32x2
__device__ __forceinline__ u64 bf2(u32 v) {
    u32 lo = v << 16;
    u32 hi = v & 0xFFFF0000u;
    u64 r;
    asm("mov.b64 %0, {%1, %2};" : "=l"(r) : "r"(lo), "r"(hi));
    return r;
}
__device__ __forceinline__ u64 pack2(float a, float b) {
    u64 r;
    asm("mov.b64 %0, {%1, %2};" : "=l"(r) : "f"(a), "f"(b));
    return r;
}
__device__ __forceinline__ u64 dup2(float a) { return pack2(a, a); }
__device__ __forceinline__ void unpk(u64 v, float& a, float& b) {
    asm("mov.b64 {%0, %1}, %2;" : "=f"(a), "=f"(b) : "l"(v));
}
__device__ __forceinline__ u32 pkbf(float a, float b) {
    __nv_bfloat162 h = __floats2bfloat162_rn(a, b);  // .x=a (low), .y=b (high)
    return *reinterpret_cast<u32*>(&h);
}
__device__ __forceinline__ float relu(float a) { return fmaxf(a, 0.f); }

__global__ __launch_bounds__(THREADS, 1)
void koopman_kernel(const float* __restrict__ x,
                    const float* __restrict__ cW1, const float* __restrict__ cb1,
                    const float* __restrict__ cW2, const float* __restrict__ cb2,
                    const float* __restrict__ rW1, const float* __restrict__ rb1,
                    const float* __restrict__ rW2, const float* __restrict__ rb2,
                    float* __restrict__ out) {
    extern __shared__ float sm[];
    u32* scw1 = (u32*)(sm + OFF_CW1);
    u32* scw2 = (u32*)(sm + OFF_CW2);
    u32* srw1 = (u32*)(sm + OFF_RW1);
    u32* srw2 = (u32*)(sm + OFF_RW2);
    float* sy  = sm + OFF_Y;
    float* sh1 = sm + OFF_H1;
    float* sr1 = sm + OFF_R1;

    const int tid = threadIdx.x;

    // ---- pack weights to bf16x2 pair-interleaved layout ----
    for (int i = tid; i < 64 * 192; i += THREADS) {
        int q = i / 192, k = i % 192;
        scw1[q * P_W1 + k] = pkbf(cW1[(2 * q) * 192 + k], cW1[(2 * q + 1) * 192 + k]);
    }
    for (int i = tid; i < 64 * 128; i += THREADS) {
        int q = i / 128, k = i % 128;
        scw2[q * P_W2 + k] = pkbf(cW2[(2 * q) * 128 + k], cW2[(2 * q + 1) * 128 + k]);
    }
    for (int i = tid; i < 32 * 192; i += THREADS) {
        int q = i / 192, k = i % 192;
        srw1[q * P_W1 + k] = pkbf(rW1[(2 * q) * 192 + k], rW1[(2 * q + 1) * 192 + k]);
    }
    for (int i = tid; i < 32 * 64; i += THREADS) {
        int q = i / 64, k = i % 64;
        srw2[q * P_RW2 + k] = pkbf(rW2[(2 * q) * 64 + k], rW2[(2 * q + 1) * 64 + k]);
    }
    if (tid < 128) {
        sm[OFF_CB1 + tid] = cb1[tid];
        sm[OFF_CB2 + tid] = cb2[tid];
    }
    if (tid < 64) {
        sm[OFF_RB1 + tid] = rb1[tid];
        sm[OFF_RB2 + tid] = rb2[tid];
    }

    // ---- init duplicated y state from x[:, 0, :] ----
    const int rowBase = blockIdx.x * ROWS;
    for (int i = tid; i < ROWS * KD; i += THREADS) {
        int r = i / KD, c = i % KD;
        float v = x[(size_t)(rowBase + r) * (TSTEPS * KD) + c];
        sy[c * P_ACT + 2 * r]     = v;
        sy[c * P_ACT + 2 * r + 1] = v;
    }
    __syncthreads();

    const int lane = tid & 31;
    const int r0   = (tid >> 5) * 4;          // 8 warps * 4 rows = 32 rows
    const float* ysA = sy  + 2 * r0;
    const float* h1A = sh1 + 2 * r0;
    const float* r1A = sr1 + 2 * r0;
    const u32* w1a  = scw1 + lane * P_W1;
    const u32* w1b  = scw1 + (lane + 32) * P_W1;
    const u32* w2a  = scw2 + lane * P_W2;
    const u32* w2b  = scw2 + (lane + 32) * P_W2;
    const u32* rw1a = srw1 + lane * P_W1;
    const u32* rw2a = srw2 + lane * P_RW2;

    const u64 bc1a = pack2(sm[OFF_CB1 + 2 * lane],      sm[OFF_CB1 + 2 * lane + 1]);
    const u64 bc1b = pack2(sm[OFF_CB1 + 2 * lane + 64], sm[OFF_CB1 + 2 * lane + 65]);
    const u64 bc2a = pack2(sm[OFF_CB2 + 2 * lane],      sm[OFF_CB2 + 2 * lane + 1]);
    const u64 bc2b = pack2(sm[OFF_CB2 + 2 * lane + 64], sm[OFF_CB2 + 2 * lane + 65]);
    const u64 br1  = pack2(sm[OFF_RB1 + 2 * lane],      sm[OFF_RB1 + 2 * lane + 1]);
    const u64 br2  = pack2(sm[OFF_RB2 + 2 * lane],      sm[OFF_RB2 + 2 * lane + 1]);

    float* outRow = out + (size_t)rowBase * TSTEPS * KD;

    for (int t = 0; t < TSTEPS; ++t) {
        // ---- Phase A (merged): h1 = relu(y@cW1^T+cb1), r1 = relu(y@rW1^T+rb1) ----
        u64 acc[4][2];
        u64 accr[4];
#pragma unroll
        for (int rr = 0; rr < 4; ++rr) { acc[rr][0] = bc1a; acc[rr][1] = bc1b; accr[rr] = br1; }
#pragma unroll 2
        for (int k = 0; k < 192; k += 2) {
            u64 wvA = *(const u64*)(w1a + k);
            u64 wvB = *(const u64*)(w1b + k);
            u64 wvR = *(const u64*)(rw1a + k);
            ulonglong2 y0 = *(const ulonglong2*)(ysA + k * P_ACT);          // rows r0,r0+1 (k)
            ulonglong2 y1 = *(const ulonglong2*)(ysA + k * P_ACT + 4);      // rows r0+2,r0+3 (k)
            ulonglong2 z0 = *(const ulonglong2*)(ysA + (k + 1) * P_ACT);
            ulonglong2 z1 = *(const ulonglong2*)(ysA + (k + 1) * P_ACT + 4);
            u64 a0 = bf2((u32)wvA), a1 = bf2((u32)(wvA >> 32));
            u64 b0 = bf2((u32)wvB), b1 = bf2((u32)(wvB >> 32));
            u64 c0 = bf2((u32)wvR), c1 = bf2((u32)(wvR >> 32));
            acc[0][0] = ffma2(y0.x, a0, acc[0][0]); acc[0][1] = ffma2(y0.x, b0, acc[0][1]); accr[0] = ffma2(y0.x, c0, accr[0]);
            acc[1][0] = ffma2(y0.y, a0, acc[1][0]); acc[1][1] = ffma2(y0.y, b0, acc[1][1]); accr[1] = ffma2(y0.y, c0, accr[1]);
            acc[2][0] = ffma2(y1.x, a0, acc[2][0]); acc[2][1] = ffma2(y1.x, b0, acc[2][1]); accr[2] = ffma2(y1.x, c0, accr[2]);
            acc[3][0] = ffma2(y1.y, a0, acc[3][0]); acc[3][1] = ffma2(y1.y, b0, acc[3][1]); accr[3] = ffma2(y1.y, c0, accr[3]);
            acc[0][0] = ffma2(z0.x, a1, acc[0][0]); acc[0][1] = ffma2(z0.x, b1, acc[0][1]); accr[0] = ffma2(z0.x, c1, accr[0]);
            acc[1][0] = ffma2(z0.y, a1, acc[1][0]); acc[1][1] = ffma2(z0.y, b1, acc[1][1]); accr[1] = ffma2(z0.y, c1, accr[1]);
            acc[2][0] = ffma2(z1.x, a1, acc[2][0]); acc[2][1] = ffma2(z1.x, b1, acc[2][1]); accr[2] = ffma2(z1.x, c1, accr[2]);
            acc[3][0] = ffma2(z1.y, a1, acc[3][0]); acc[3][1] = ffma2(z1.y, b1, acc[3][1]); accr[3] = ffma2(z1.y, c1, accr[3]);
        }
        // ---- A epilogue: relu + duplicated stores (STS.128 of 2 dup pairs) ----
#pragma unroll
        for (int j = 0; j < 2; ++j) {
            float a0, a1, a2, a3, b0, b1, b2, b3;
            unpk(acc[0][j], a0, b0); unpk(acc[1][j], a1, b1);
            unpk(acc[2][j], a2, b2); unpk(acc[3][j], a3, b3);
            int ca = 2 * (lane + 32 * j);
            float* pa = sh1 + ca * P_ACT + 2 * r0;
            float* pb = sh1 + (ca + 1) * P_ACT + 2 * r0;
            *(float4*)(pa)     = make_float4(relu(a0), relu(a0), relu(a1), relu(a1));
            *(float4*)(pa + 4) = make_float4(relu(a2), relu(a2), relu(a3), relu(a3));
            *(float4*)(pb)     = make_float4(relu(b0), relu(b0), relu(b1), relu(b1));
            *(float4*)(pb + 4) = make_float4(relu(b2), relu(b2), relu(b3), relu(b3));
        }
        {
            float a0, a1, a2, a3, b0, b1, b2, b3;
            unpk(accr[0], a0, b0); unpk(accr[1], a1, b1);
            unpk(accr[2], a2, b2); unpk(accr[3], a3, b3);
            float* pa = sr1 + (2 * lane) * P_ACT + 2 * r0;
            float* pb = sr1 + (2 * lane + 1) * P_ACT + 2 * r0;
            *(float4*)(pa)     = make_float4(relu(a0), relu(a0), relu(a1), relu(a1));
            *(float4*)(pa + 4) = make_float4(relu(a2), relu(a2), relu(a3), relu(a3));
            *(float4*)(pb)     = make_float4(relu(b0), relu(b0), relu(b1), relu(b1));
            *(float4*)(pb + 4) = make_float4(relu(b2), relu(b2), relu(b3), relu(b3));
        }
        __syncwarp();   // rows are warp-partitioned: A-epi -> B is warp-local

        // ---- Phase B: h = h1 @ cW2^T + cb2 ----
#pragma unroll
        for (int rr = 0; rr < 4; ++rr) { acc[rr][0] = bc2a; acc[rr][1] = bc2b; }
#pragma unroll 2
        for (int k = 0; k < 128; k += 2) {
            u64 wvA = *(const u64*)(w2a + k);
            u64 wvB = *(const u64*)(w2b + k);
            ulonglong2 y0 = *(const ulonglong2*)(h1A + k * P_ACT);
            ulonglong2 y1 = *(const ulonglong2*)(h1A + k * P_ACT + 4);
            ulonglong2 z0 = *(const ulonglong2*)(h1A + (k + 1) * P_ACT);
            ulonglong2 z1 = *(const ulonglong2*)(h1A + (k + 1) * P_ACT + 4);
            u64 a0 = bf2((u32)wvA), a1 = bf2((u32)(wvA >> 32));
            u64 b0 = bf2((u32)wvB), b1 = bf2((u32)(wvB >> 32));
            acc[0][0] = ffma2(y0.x, a0, acc[0][0]); acc[0][1] = ffma2(y0.x, b0, acc[0][1]);
            acc[1][0] = ffma2(y0.y, a0, acc[1][0]); acc[1][1] = ffma2(y0.y, b0, acc[1][1]);
            acc[2][0] = ffma2(y1.x, a0, acc[2][0]); acc[2][1] = ffma2(y1.x, b0, acc[2][1]);
            acc[3][0] = ffma2(y1.y, a0, acc[3][0]); acc[3][1] = ffma2(y1.y, b0, acc[3][1]);
            acc[0][0] = ffma2(z0.x, a1, acc[0][0]); acc[0][1] = ffma2(z0.x, b1, acc[0][1]);
            acc[1][0] = ffma2(z0.y, a1, acc[1][0]); acc[1][1] = ffma2(z0.y, b1, acc[1][1]);
            acc[2][0] = ffma2(z1.x, a1, acc[2][0]); acc[2][1] = ffma2(z1.x, b1, acc[2][1]);
            acc[3][0] = ffma2(z1.y, a1, acc[3][0]); acc[3][1] = ffma2(z1.y, b1, acc[3][1]);
        }
        // ---- Phase B: re = r1 @ rW2^T + rb2 ----
#pragma unroll
        for (int rr = 0; rr < 4; ++rr) accr[rr] = br2;
#pragma unroll 2
        for (int k = 0; k < 64; k += 2) {
            u64 wvR = *(const u64*)(rw2a + k);
            ulonglong2 y0 = *(const ulonglong2*)(r1A + k * P_ACT);
            ulonglong2 y1 = *(const ulonglong2*)(r1A + k * P_ACT + 4);
            ulonglong2 z0 = *(const ulonglong2*)(r1A + (k + 1) * P_ACT);
            ulonglong2 z1 = *(const ulonglong2*)(r1A + (k + 1) * P_ACT + 4);
            u64 c0 = bf2((u32)wvR), c1 = bf2((u32)(wvR >> 32));
            accr[0] = ffma2(y0.x, c0, accr[0]);
            accr[1] = ffma2(y0.y, c0, accr[1]);
            accr[2] = ffma2(y1.x, c0, accr[2]);
            accr[3] = ffma2(y1.y, c0, accr[3]);
            accr[0] = ffma2(z0.x, c1, accr[0]);
            accr[1] = ffma2(z0.y, c1, accr[1]);
            accr[2] = ffma2(z1.x, c1, accr[2]);
            accr[3] = ffma2(z1.y, c1, accr[3]);
        }

        // ---- Phase C: apply Koopman operator, update y in place, write out ----
#pragma unroll
        for (int j = 0; j < 2; ++j) {
            int q = lane + 32 * j;
#pragma unroll
            for (int rr = 0; rr < 4; ++rr) {
                float mu, om;
                unpk(acc[rr][j], mu, om);
                float e = __expf(DT * mu);
                float s, c;
                __sincosf(DT * om, &s, &c);
                int yi = 2 * (r0 + rr);
                float ye = sy[(2 * q) * P_ACT + yi];
                float yo = sy[(2 * q + 1) * P_ACT + yi];
                float ne = e * (c * ye - s * yo);
                float no = e * (s * ye + c * yo);
                *(u64*)(sy + (2 * q) * P_ACT + yi)     = dup2(ne);
                *(u64*)(sy + (2 * q + 1) * P_ACT + yi) = dup2(no);
                *(float2*)(outRow + (size_t)(r0 + rr) * (TSTEPS * KD) + (size_t)t * KD + 2 * q)
                    = make_float2(ne, no);
            }
        }
#pragma unroll
        for (int rr = 0; rr < 4; ++rr) {
            float ra, rb;
            unpk(accr[rr], ra, rb);
            int c0 = 128 + 2 * lane;
            int yi = 2 * (r0 + rr);
            float ya = sy[c0 * P_ACT + yi];
            float yb = sy[(c0 + 1) * P_ACT + yi];
            float na = ya * __expf(DT * ra);
            float nb = yb * __expf(DT * rb);
            *(u64*)(sy + c0 * P_ACT + yi)       = dup2(na);
            *(u64*)(sy + (c0 + 1) * P_ACT + yi) = dup2(nb);
            *(float2*)(outRow + (size_t)(r0 + rr) * (TSTEPS * KD) + (size_t)t * KD + c0)
                = make_float2(na, nb);
        }
        __syncwarp();   // C -> next A is also warp-local
    }
}

extern "C" void kernel_launch(void* const* d_in, const int* in_sizes, int n_in,
                              void* d_out, int out_size) {
    const float* x   = (const float*)d_in[0];
    const float* cW1 = (const float*)d_in[1];
    const float* cb1 = (const float*)d_in[2];
    const float* cW2 = (const float*)d_in[3];
    const float* cb2 = (const float*)d_in[4];
    const float* rW1 = (const float*)d_in[5];
    const float* rb1 = (const float*)d_in[6];
    const float* rW2 = (const float*)d_in[7];
    const float* rb2 = (const float*)d_in[8];
    float* out = (float*)d_out;

    cudaFuncSetAttribute(koopman_kernel,
                         cudaFuncAttributeMaxDynamicSharedMemorySize, SMEM_BYTES);
    koopman_kernel<<<CTAS, THREADS, SMEM_BYTES>>>(x, cW1, cb1, cW2, cb2,
                                                  rW1, rb1, rW2, rb2, out);
}